// round 9
// baseline (speedup 1.0000x reference)
#include <cuda_runtime.h>
#include <math.h>

#define D_MODEL   1024
#define SEQ_LEN   32768
#define NBLK_A    512                   // phase-A blocks (single wave at occ 4)
#define LPB       64                    // l's per block
#define LPW       8                     // l's per warp (8 warps/block)
#define NBLK_BC   512

#define TWO_PI    6.283185307179586f
#define INV_2PI   0.15915494309189535f
#define MAGIC     12582912.0f           // 1.5 * 2^23
#define C1_2PI    6.28318548202514648f  // fl32(2*pi)
#define INV1023   (1.0f / 1023.0f)

typedef unsigned long long ull;

// Scratch (device globals; no allocation in kernel_launch)
// g_part[slice][i], i = m*32 + k packs (d=32k+2m, 32k+2m+1), sign-twisted.
__device__ ull g_part[NBLK_A * 512];               // 2 MB
__device__ __align__(16) float g_signal[D_MODEL];
__device__ unsigned g_ctrA = 0, g_ctrD = 0;

// ---------------- packed f32x2 helpers --------------------------------------
__device__ __forceinline__ ull fma2(ull a, ull b, ull c) {
    ull d; asm("fma.rn.f32x2 %0,%1,%2,%3;" : "=l"(d) : "l"(a), "l"(b), "l"(c)); return d;
}
__device__ __forceinline__ ull add2(ull a, ull b) {
    ull d; asm("add.rn.f32x2 %0,%1,%2;" : "=l"(d) : "l"(a), "l"(b)); return d;
}
__device__ __forceinline__ ull pk2(float lo, float hi) {
    ull d; asm("mov.b64 %0,{%1,%2};" : "=l"(d) : "f"(lo), "f"(hi)); return d;
}
__device__ __forceinline__ float2 unpk(ull v) {
    float2 r; asm("mov.b64 {%0,%1},%2;" : "=f"(r.x), "=f"(r.y) : "l"(v)); return r;
}

// ---------------------------------------------------------------------------
// Kernel A: packed-pair Chebyshev recurrence over d, TWO interleaved l-chains
// per iteration for ILP. Lane k owns d=32k..32k+31 as 16 packed pairs.
// ---------------------------------------------------------------------------
__global__ void __launch_bounds__(256, 4)
sinsum_kernel(const float* __restrict__ inputs) {
    __shared__ float4 co[LPB];        // (a, a*log1p(l), 2cos(dl), 2cos(2dl))
    __shared__ ull    sred[8 * 512];  // 32KB packed cross-warp buffer

    const int tid = threadIdx.x;
    const int w   = tid >> 5;
    const int k   = tid & 31;

    if (tid < LPB) {
        const int l = blockIdx.x * LPB + tid;
        float x  = inputs[l];
        float a  = TWO_PI * x;
        float p  = log1pf((float)l);
        float dl = a * INV1023;
        float d2 = dl * dl;
        float u2 = 4.0f * d2;                         // (2*dl)^2
        float c  = fmaf(d2, fmaf(d2, fmaf(d2, -(1.0f/360.0f), (1.0f/12.0f)), -1.0f), 2.0f);
        float c2 = fmaf(u2, fmaf(u2, fmaf(u2, -(1.0f/360.0f), (1.0f/12.0f)), -1.0f), 2.0f);
        co[tid]  = make_float4(a, a * p, c, c2);
    }
    __syncthreads();

    const float tk = (float)(32 * k) * INV1023;

    ull acc[16];
#pragma unroll
    for (int m = 0; m < 16; ++m) acc[m] = 0ull;

#pragma unroll 1
    for (int jp = 0; jp < LPW / 2; ++jp) {
        float4 CA = co[w * LPW + 2 * jp];
        float4 CB = co[w * LPW + 2 * jp + 1];

        // --- seeds for chain A and chain B (independent) ---
        float phiA = fmaf(CA.x, tk, CA.y);
        float phiB = fmaf(CB.x, tk, CB.y);
        float yA   = fmaf(phiA, INV_2PI, MAGIC);
        float yB   = fmaf(phiB, INV_2PI, MAGIC);
        float rA   = fmaf(yA - MAGIC, -C1_2PI, phiA);
        float rB   = fmaf(yB - MAGIC, -C1_2PI, phiB);
        float dlA  = CA.x * INV1023;
        float dlB  = CB.x * INV1023;
        float sA0  = __sinf(rA);
        float sB0  = __sinf(rB);
        float sA1  = __sinf(rA + dlA);
        float sB1  = __sinf(rB + dlB);
        float sA2  = fmaf(CA.z, sA1, -sA0);
        float sB2  = fmaf(CB.z, sB1, -sB0);
        float sA3  = fmaf(CA.z, sA2, -sA1);
        float sB3  = fmaf(CB.z, sB2, -sB1);

        ull a0 = pk2(sA0, sA1), a1 = pk2(sA2, sA3);
        ull b0 = pk2(sB0, sB1), b1 = pk2(sB2, sB3);
        ull cAp = pk2(CA.w, CA.w), cAn = pk2(-CA.w, -CA.w);
        ull cBp = pk2(CB.w, CB.w), cBn = pk2(-CB.w, -CB.w);

        acc[0] = add2(acc[0], add2(a0, b0));
        acc[1] = add2(acc[1], add2(a1, b1));

#pragma unroll
        for (int m = 2; m < 16; ++m) {
            // sign-twisted: a_m = fma2(m odd ? +c2 : -c2, a_{m-1}, a_{m-2})
            ull an = fma2((m & 1) ? cAp : cAn, a1, a0);
            ull bn = fma2((m & 1) ? cBp : cBn, b1, b0);
            acc[m] = add2(acc[m], add2(an, bn));
            a0 = a1; a1 = an;
            b0 = b1; b1 = bn;
        }
    }

    // Epilogue: packed cross-warp reduce.
#pragma unroll
    for (int m = 0; m < 16; ++m)
        sred[w * 512 + m * 32 + k] = acc[m];
    __syncthreads();

#pragma unroll
    for (int rep = 0; rep < 2; ++rep) {
        const int i = tid + rep * 256;
        ull s = sred[i];
#pragma unroll
        for (int ww = 1; ww < 8; ++ww)
            s = add2(s, sred[ww * 512 + i]);
        g_part[blockIdx.x * 512 + i] = s;             // STG.64 coalesced
    }
}

// ---------------------------------------------------------------------------
// Kernel BC: 512 blocks x 256 threads.
// Prefetch W (2 rows/block, 2 float4/thread = 8 regs, physically holdable) ->
// phase B (block b reduces packed column b over 512 slices) -> grid sync ->
// phase C (GEMV on preloaded registers).
// ---------------------------------------------------------------------------
__global__ void __launch_bounds__(256, 4)
bc_kernel(const float* __restrict__ W, const float* __restrict__ bias,
          float* __restrict__ out) {
    __shared__ ull   sbu[8];
    __shared__ float cred[8];

    const int tid  = threadIdx.x;
    const int b    = blockIdx.x;
    const int half = tid >> 7;            // 0,1 -> row 2b+half
    const int cidx = tid & 127;           // column quarter index
    const int lane = tid & 31;
    const int w    = tid >> 5;

    // ---- W prefetch: 2 float4 per thread (kept live through phase B) ----
    const float4* w4 = (const float4*)(W + (2 * b + half) * D_MODEL);
    const float4 wA = w4[cidx];
    const float4 wB = w4[cidx + 128];

    // ---- phase B: reduce packed column b over 512 slices -----------------
    {
        ull v = add2(g_part[tid * 512 + b], g_part[(tid + 256) * 512 + b]);
#pragma unroll
        for (int off = 16; off > 0; off >>= 1)
            v = add2(v, __shfl_down_sync(0xffffffffu, v, off));
        if (lane == 0) sbu[w] = v;
        __syncthreads();
        if (tid == 0) {
            ull tot = add2(add2(add2(sbu[0], sbu[1]), add2(sbu[2], sbu[3])),
                           add2(add2(sbu[4], sbu[5]), add2(sbu[6], sbu[7])));
            const int m  = b >> 5;
            const int kk = b & 31;
            const float sg = ((m >> 1) & 1) ? -1.0f : 1.0f;   // undo sigma
            float2 v2 = unpk(tot);
            const int d0 = 32 * kk + 2 * m;
            g_signal[d0]     = sg * v2.x;
            g_signal[d0 + 1] = sg * v2.y;
            __threadfence();
        }
    }

    // ---- deterministic grid sync (integer counter, self-resetting) ------
    __syncthreads();
    if (tid == 0) {
        atomicAdd(&g_ctrA, 1u);
        while (*(volatile unsigned*)&g_ctrA < NBLK_BC) __nanosleep(32);
        __threadfence();
    }
    __syncthreads();

    // ---- phase C: GEMV on preloaded W registers ---------------------------
    {
        const float4* sg4 = (const float4*)g_signal;   // L2-hot
        float4 sA = sg4[cidx];
        float4 sB = sg4[cidx + 128];
        float acc = wA.x * sA.x;
        acc = fmaf(wA.y, sA.y, acc); acc = fmaf(wA.z, sA.z, acc);
        acc = fmaf(wA.w, sA.w, acc);
        acc = fmaf(wB.x, sB.x, acc); acc = fmaf(wB.y, sB.y, acc);
        acc = fmaf(wB.z, sB.z, acc); acc = fmaf(wB.w, sB.w, acc);
#pragma unroll
        for (int off = 16; off > 0; off >>= 1)
            acc += __shfl_down_sync(0xffffffffu, acc, off);
        if (lane == 0) cred[w] = acc;
        __syncthreads();
        if (tid == 0)
            out[2 * b]     = (cred[0] + cred[1]) + (cred[2] + cred[3]) + bias[2 * b];
        if (tid == 128)
            out[2 * b + 1] = (cred[4] + cred[5]) + (cred[6] + cred[7]) + bias[2 * b + 1];
    }

    // ---- counter cleanup so graph replays start from zero ---------------
    if (tid == 0) {
        unsigned old = atomicAdd(&g_ctrD, 1u);
        if (old == NBLK_BC - 1) {
            g_ctrA = 0;
            g_ctrD = 0;
            __threadfence();
        }
    }
}

// ---------------------------------------------------------------------------
extern "C" void kernel_launch(void* const* d_in, const int* in_sizes, int n_in,
                              void* d_out, int out_size) {
    const float* inputs = (const float*)d_in[0];   // [32768]
    const float* W      = (const float*)d_in[1];   // [1024,1024]
    const float* b      = (const float*)d_in[2];   // [1024]
    float*       out    = (float*)d_out;           // [1024]

    sinsum_kernel<<<NBLK_A, 256>>>(inputs);
    bc_kernel<<<NBLK_BC, 256>>>(W, b, out);
    (void)in_sizes; (void)n_in; (void)out_size;
}

// round 10
// speedup vs baseline: 1.2718x; 1.2718x over previous
#include <cuda_runtime.h>
#include <math.h>

#define D_MODEL   1024
#define SEQ_LEN   32768
#define NBLK_A    512                   // phase-A blocks (single wave at occ 4)
#define LPB       64                    // l's per block
#define LPW       8                     // l's per warp (8 warps/block)

#define TWO_PI    6.283185307179586f
#define INV_2PI   0.15915494309189535f
#define MAGIC     12582912.0f           // 1.5 * 2^23
#define C1_2PI    6.28318548202514648f  // fl32(2*pi)
#define INV1023   (1.0f / 1023.0f)

typedef unsigned long long ull;

// Scratch (device globals; no allocation in kernel_launch)
// TRANSPOSED: g_part[col][slice]; col i = m*32+k packs d=(32k+2m, 32k+2m+1),
// sign-twisted by sigma_m. A stores scattered (hidden), B loads coalesced.
__device__ ull g_part[512 * NBLK_A];               // 2 MB
__device__ __align__(16) float g_signal[D_MODEL];

// ---------------- packed f32x2 helpers --------------------------------------
__device__ __forceinline__ ull fma2(ull a, ull b, ull c) {
    ull d; asm("fma.rn.f32x2 %0,%1,%2,%3;" : "=l"(d) : "l"(a), "l"(b), "l"(c)); return d;
}
__device__ __forceinline__ ull add2(ull a, ull b) {
    ull d; asm("add.rn.f32x2 %0,%1,%2;" : "=l"(d) : "l"(a), "l"(b)); return d;
}
__device__ __forceinline__ ull pk2(float lo, float hi) {
    ull d; asm("mov.b64 %0,{%1,%2};" : "=l"(d) : "f"(lo), "f"(hi)); return d;
}
__device__ __forceinline__ float2 unpk(ull v) {
    float2 r; asm("mov.b64 {%0,%1},%2;" : "=f"(r.x), "=f"(r.y) : "l"(v)); return r;
}

// ---------------------------------------------------------------------------
// Kernel A: packed-pair Chebyshev recurrence over d, TWO interleaved l-chains
// per iteration for ILP. Lane k owns d=32k..32k+31 as 16 packed pairs.
// ---------------------------------------------------------------------------
__global__ void __launch_bounds__(256, 4)
sinsum_kernel(const float* __restrict__ inputs) {
    __shared__ float4 co[LPB];        // (a, a*log1p(l), 2cos(dl), 2cos(2dl))
    __shared__ ull    sred[8 * 512];  // 32KB packed cross-warp buffer

    const int tid = threadIdx.x;
    const int w   = tid >> 5;
    const int k   = tid & 31;

    if (tid < LPB) {
        const int l = blockIdx.x * LPB + tid;
        float x  = inputs[l];
        float a  = TWO_PI * x;
        float p  = log1pf((float)l);
        float dl = a * INV1023;
        float d2 = dl * dl;
        float u2 = 4.0f * d2;                         // (2*dl)^2
        float c  = fmaf(d2, fmaf(d2, fmaf(d2, -(1.0f/360.0f), (1.0f/12.0f)), -1.0f), 2.0f);
        float c2 = fmaf(u2, fmaf(u2, fmaf(u2, -(1.0f/360.0f), (1.0f/12.0f)), -1.0f), 2.0f);
        co[tid]  = make_float4(a, a * p, c, c2);
    }
    __syncthreads();

    const float tk = (float)(32 * k) * INV1023;

    ull acc[16];
#pragma unroll
    for (int m = 0; m < 16; ++m) acc[m] = 0ull;

#pragma unroll 1
    for (int jp = 0; jp < LPW / 2; ++jp) {
        float4 CA = co[w * LPW + 2 * jp];
        float4 CB = co[w * LPW + 2 * jp + 1];

        // --- seeds for chain A and chain B (independent) ---
        float phiA = fmaf(CA.x, tk, CA.y);
        float phiB = fmaf(CB.x, tk, CB.y);
        float yA   = fmaf(phiA, INV_2PI, MAGIC);
        float yB   = fmaf(phiB, INV_2PI, MAGIC);
        float rA   = fmaf(yA - MAGIC, -C1_2PI, phiA);
        float rB   = fmaf(yB - MAGIC, -C1_2PI, phiB);
        float dlA  = CA.x * INV1023;
        float dlB  = CB.x * INV1023;
        float sA0  = __sinf(rA);
        float sB0  = __sinf(rB);
        float sA1  = __sinf(rA + dlA);
        float sB1  = __sinf(rB + dlB);
        float sA2  = fmaf(CA.z, sA1, -sA0);
        float sB2  = fmaf(CB.z, sB1, -sB0);
        float sA3  = fmaf(CA.z, sA2, -sA1);
        float sB3  = fmaf(CB.z, sB2, -sB1);

        ull a0 = pk2(sA0, sA1), a1 = pk2(sA2, sA3);
        ull b0 = pk2(sB0, sB1), b1 = pk2(sB2, sB3);
        ull cAp = pk2(CA.w, CA.w), cAn = pk2(-CA.w, -CA.w);
        ull cBp = pk2(CB.w, CB.w), cBn = pk2(-CB.w, -CB.w);

        acc[0] = add2(acc[0], add2(a0, b0));
        acc[1] = add2(acc[1], add2(a1, b1));

#pragma unroll
        for (int m = 2; m < 16; ++m) {
            // sign-twisted: a_m = fma2(m odd ? +c2 : -c2, a_{m-1}, a_{m-2})
            ull an = fma2((m & 1) ? cAp : cAn, a1, a0);
            ull bn = fma2((m & 1) ? cBp : cBn, b1, b0);
            acc[m] = add2(acc[m], add2(an, bn));
            a0 = a1; a1 = an;
            b0 = b1; b1 = bn;
        }
    }

    // Epilogue: packed cross-warp reduce, then transposed (scattered) store.
#pragma unroll
    for (int m = 0; m < 16; ++m)
        sred[w * 512 + m * 32 + k] = acc[m];
    __syncthreads();

#pragma unroll
    for (int rep = 0; rep < 2; ++rep) {
        const int i = tid + rep * 256;
        ull s = sred[i];
#pragma unroll
        for (int ww = 1; ww < 8; ++ww)
            s = add2(s, sred[ww * 512 + i]);
        g_part[i * NBLK_A + blockIdx.x] = s;          // [col][slice]
    }
}

// ---------------------------------------------------------------------------
// Kernel B: reduce each packed column over 512 slices (coalesced), undo
// sigma, emit signal. 64 blocks x 256 threads; warp per column.
// ---------------------------------------------------------------------------
__global__ void __launch_bounds__(256)
reduce_kernel() {
    const int tid  = threadIdx.x;
    const int lane = tid & 31;
    const int col  = blockIdx.x * 8 + (tid >> 5);     // 0..511

    const ull* src = &g_part[col * NBLK_A];
    ull s = add2(src[lane], src[lane + 32]);
#pragma unroll
    for (int j = 2; j < 16; j += 2)
        s = add2(s, add2(src[lane + 32 * j], src[lane + 32 * (j + 1)]));
#pragma unroll
    for (int off = 16; off > 0; off >>= 1)
        s = add2(s, __shfl_down_sync(0xffffffffu, s, off));

    if (lane == 0) {
        const int m  = col >> 5;
        const int kk = col & 31;
        const float sg = ((m >> 1) & 1) ? -1.0f : 1.0f;   // undo sigma_m
        float2 v = unpk(s);
        const int d0 = 32 * kk + 2 * m;
        g_signal[d0]     = sg * v.x;
        g_signal[d0 + 1] = sg * v.y;
    }
}

// ---------------------------------------------------------------------------
// Kernel C: GEMV out = signal @ W^T + b. 256 blocks x 128 thr, warp per row.
// ---------------------------------------------------------------------------
__global__ void __launch_bounds__(128)
gemv_kernel(const float* __restrict__ W, const float* __restrict__ bias,
            float* __restrict__ out) {
    __shared__ __align__(16) float ssig[D_MODEL];

    const int tid = threadIdx.x;
#pragma unroll
    for (int i = tid; i < D_MODEL / 4; i += 128)
        ((float4*)ssig)[i] = ((const float4*)g_signal)[i];
    __syncthreads();

    const int warp = tid >> 5;
    const int lane = tid & 31;
    const int row  = blockIdx.x * 4 + warp;

    const float4* w4 = (const float4*)(W + row * D_MODEL);
    float acc = 0.0f;
#pragma unroll
    for (int kk = lane; kk < D_MODEL / 4; kk += 32) {
        float4 wv = w4[kk];
        float4 sv = ((const float4*)ssig)[kk];
        acc = fmaf(wv.x, sv.x, acc);
        acc = fmaf(wv.y, sv.y, acc);
        acc = fmaf(wv.z, sv.z, acc);
        acc = fmaf(wv.w, sv.w, acc);
    }
#pragma unroll
    for (int off = 16; off > 0; off >>= 1)
        acc += __shfl_down_sync(0xffffffffu, acc, off);

    if (lane == 0) out[row] = acc + bias[row];
}

// ---------------------------------------------------------------------------
extern "C" void kernel_launch(void* const* d_in, const int* in_sizes, int n_in,
                              void* d_out, int out_size) {
    const float* inputs = (const float*)d_in[0];   // [32768]
    const float* W      = (const float*)d_in[1];   // [1024,1024]
    const float* b      = (const float*)d_in[2];   // [1024]
    float*       out    = (float*)d_out;           // [1024]

    sinsum_kernel<<<NBLK_A, 256>>>(inputs);
    reduce_kernel<<<64, 256>>>();
    gemv_kernel<<<D_MODEL / 4, 128>>>(W, b, out);
    (void)in_sizes; (void)n_in; (void)out_size;
}